// round 4
// baseline (speedup 1.0000x reference)
#include <cuda_runtime.h>
#include <cstdint>

#define BB   8
#define SS   4096
#define HIDD 1024
#define HH   16
#define DHH  64

#define MT        128                 // rows per k1 block
#define KC        32                  // k-chunk
#define NC        (HIDD / KC)         // 32 chunks
#define K1_CHUNKS 32                  // tiles per batch (SS/MT)
#define K1_BLOCKS (BB * K1_CHUNKS)    // 256

// ---------- static scratch (no allocations allowed) ----------
__device__ float g_scratch[(size_t)K1_BLOCKS * HH * HIDD]; // 16.8 MB
__device__ float hbar_scratch[(size_t)K1_BLOCKS * HIDD];   // 1 MB
__device__ float wqk_eff[2 * HH * HIDD];                   // [vec][e], vec<16: q, >=16: k
__device__ float qs_buf[(size_t)BB * SS * HH];             // 2 MB
__device__ float hbar_final[BB * HIDD];
__device__ float kv_buf[BB * HH * DHH];
__device__ float mv_buf[BB * HH * DHH];
__device__ float invlen_buf[BB];

typedef unsigned long long u64;

__device__ __forceinline__ u64 ffma2(u64 a, u64 b, u64 c) {
    u64 d;
    asm("fma.rn.f32x2 %0, %1, %2, %3;" : "=l"(d) : "l"(a), "l"(b), "l"(c));
    return d;
}
__device__ __forceinline__ u64 pack2(float x, float y) {
    u64 r; asm("mov.b64 %0, {%1,%2};" : "=l"(r) : "f"(x), "f"(y)); return r;
}
__device__ __forceinline__ float2 unpack2(u64 v) {
    float2 r; asm("mov.b64 {%0,%1}, %2;" : "=f"(r.x), "=f"(r.y) : "l"(v)); return r;
}

// ---------- dynamic smem layout for k1 ----------
// As:     [2][KC][MT+2] float  = 33280 B   (transposed tile, pad 2 -> 2-way STS max)
// Bs:     [2][KC][33]  u64     = 16896 B   (weights duplicated (v,v), pad 1)
// ks_dup: [MT][16]     u64     = 16384 B
// m_dup:  [MT]         u64     =  1024 B
// m_sh:   [MT]         float   =   512 B
#define SM_AS   0
#define SM_BS   33280
#define SM_KS   (SM_BS + 16896)
#define SM_MD   (SM_KS + 16384)
#define SM_MS   (SM_MD + 1024)
#define SM_TOT  (SM_MS + 512)        // 68096 B

// ============================================================
// K0: wqk_eff[ch*16+h][e] = sum_d aw[h][d] * W[(h*64+d)][e]
// ============================================================
__global__ void k0_weff(const float* __restrict__ Wq,
                        const float* __restrict__ Wk,
                        const float* __restrict__ aw) {
    int ch = blockIdx.x >> 4, h = blockIdx.x & 15;
    const float* W = ch ? Wk : Wq;
    __shared__ float a_sh[DHH];
    if (threadIdx.x < DHH) a_sh[threadIdx.x] = aw[h * DHH + threadIdx.x];
    __syncthreads();
    for (int e = threadIdx.x; e < HIDD; e += blockDim.x) {
        float acc = 0.f;
#pragma unroll 8
        for (int d = 0; d < DHH; d++)
            acc += a_sh[d] * W[(size_t)(h * DHH + d) * HIDD + e];
        wqk_eff[(ch * HH + h) * HIDD + e] = acc;
    }
}

// ============================================================
// K1: 128-row tile per block, 256 threads, occ 2.
// Phase A: C[128x32] = tile x wqk_eff^T. Transposed As (LDS64 row pairs),
//          duplicated Bs -> inner loop 14 issues / 16 FMA. Double-buffered,
//          1 sync per chunk. Thread tile: 2 row-pairs x 4 cols.
// Phase B: g/hbar outer-product accumulation, partials to scratch.
// ============================================================
__global__ void __launch_bounds__(256, 2)
k1_main(const float* __restrict__ hidden, const float* __restrict__ mask) {
    extern __shared__ char smem_raw[];
    float (*As)[KC][MT + 2] = reinterpret_cast<float (*)[KC][MT + 2]>(smem_raw + SM_AS);
    u64   (*Bs)[KC][33]     = reinterpret_cast<u64 (*)[KC][33]>(smem_raw + SM_BS);
    u64   (*ks_dup)[16]     = reinterpret_cast<u64 (*)[16]>(smem_raw + SM_KS);
    u64*  m_dup             = reinterpret_cast<u64*>(smem_raw + SM_MD);
    float* m_sh             = reinterpret_cast<float*>(smem_raw + SM_MS);

    const int tile = blockIdx.x;
    const int b = tile >> 5;
    const int s0 = (tile & 31) * MT;
    const int tid = threadIdx.x;
    const int tx = tid & 7;              // col-group (4 cols)
    const int ty = tid >> 3;             // row-group (4 rows = 2 pairs)

    const float* Abase = hidden + ((size_t)b * SS + s0) * HIDD;

    if (tid < MT) {
        float m = mask[(size_t)b * SS + s0 + tid];
        m_sh[tid] = m;
        m_dup[tid] = pack2(m, m);
    }

    // acc[rowpair][col] : pair = (row ty*4+2rp, ty*4+2rp+1), col = tx*4+c
    u64 acc[2][4];
#pragma unroll
    for (int i = 0; i < 2; i++)
#pragma unroll
        for (int j = 0; j < 4; j++) acc[i][j] = 0ull;

    const int sv  = tid & 31;            // B staging: col
    const int skq = tid >> 5;            // B staging: k-quad

    float4 aR[4];
    float4 bR;

    // ---- prologue: stage chunk 0 into buffer 0 ----
#pragma unroll
    for (int i = 0; i < 4; i++) {
        int idx = tid + i * 256;
        int r = idx >> 3, kq = idx & 7;
        aR[i] = *(const float4*)(Abase + (size_t)r * HIDD + kq * 4);
    }
    bR = *(const float4*)(wqk_eff + (size_t)sv * HIDD + skq * 4);
#pragma unroll
    for (int i = 0; i < 4; i++) {
        int idx = tid + i * 256;
        int r = idx >> 3, kq = idx & 7;
        As[0][kq * 4 + 0][r] = aR[i].x;
        As[0][kq * 4 + 1][r] = aR[i].y;
        As[0][kq * 4 + 2][r] = aR[i].z;
        As[0][kq * 4 + 3][r] = aR[i].w;
    }
    Bs[0][skq * 4 + 0][sv] = pack2(bR.x, bR.x);
    Bs[0][skq * 4 + 1][sv] = pack2(bR.y, bR.y);
    Bs[0][skq * 4 + 2][sv] = pack2(bR.z, bR.z);
    Bs[0][skq * 4 + 3][sv] = pack2(bR.w, bR.w);
    __syncthreads();

    // ---- main loop: 1 sync per chunk, double buffered ----
#pragma unroll 1
    for (int c = 0; c < NC; c++) {
        const int cur = c & 1, nxt = cur ^ 1;
        if (c + 1 < NC) {
            int k0 = (c + 1) * KC;
#pragma unroll
            for (int i = 0; i < 4; i++) {
                int idx = tid + i * 256;
                int r = idx >> 3, kq = idx & 7;
                aR[i] = *(const float4*)(Abase + (size_t)r * HIDD + k0 + kq * 4);
            }
            bR = *(const float4*)(wqk_eff + (size_t)sv * HIDD + k0 + skq * 4);
        }
#pragma unroll
        for (int k = 0; k < KC; k++) {
            u64 a01 = *(const u64*)&As[cur][k][ty * 4];
            u64 a23 = *(const u64*)&As[cur][k][ty * 4 + 2];
            u64 b0 = Bs[cur][k][tx * 4 + 0];
            u64 b1 = Bs[cur][k][tx * 4 + 1];
            u64 b2 = Bs[cur][k][tx * 4 + 2];
            u64 b3 = Bs[cur][k][tx * 4 + 3];
            acc[0][0] = ffma2(a01, b0, acc[0][0]);
            acc[0][1] = ffma2(a01, b1, acc[0][1]);
            acc[0][2] = ffma2(a01, b2, acc[0][2]);
            acc[0][3] = ffma2(a01, b3, acc[0][3]);
            acc[1][0] = ffma2(a23, b0, acc[1][0]);
            acc[1][1] = ffma2(a23, b1, acc[1][1]);
            acc[1][2] = ffma2(a23, b2, acc[1][2]);
            acc[1][3] = ffma2(a23, b3, acc[1][3]);
        }
        if (c + 1 < NC) {
#pragma unroll
            for (int i = 0; i < 4; i++) {
                int idx = tid + i * 256;
                int r = idx >> 3, kq = idx & 7;
                As[nxt][kq * 4 + 0][r] = aR[i].x;
                As[nxt][kq * 4 + 1][r] = aR[i].y;
                As[nxt][kq * 4 + 2][r] = aR[i].z;
                As[nxt][kq * 4 + 3][r] = aR[i].w;
            }
            Bs[nxt][skq * 4 + 0][sv] = pack2(bR.x, bR.x);
            Bs[nxt][skq * 4 + 1][sv] = pack2(bR.y, bR.y);
            Bs[nxt][skq * 4 + 2][sv] = pack2(bR.z, bR.z);
            Bs[nxt][skq * 4 + 3][sv] = pack2(bR.w, bR.w);
        }
        __syncthreads();
    }

    // ---- epilogue A: mask, store qs (cols 0..15) or stage ks (cols 16..31) ----
#pragma unroll
    for (int rp = 0; rp < 2; rp++) {
        int r0 = ty * 4 + rp * 2;
        int r1 = r0 + 1;
        float m0 = m_sh[r0], m1 = m_sh[r1];
        float2 v0 = unpack2(acc[rp][0]);
        float2 v1 = unpack2(acc[rp][1]);
        float2 v2 = unpack2(acc[rp][2]);
        float2 v3 = unpack2(acc[rp][3]);
        if (tx < 4) {
            *(float4*)(qs_buf + ((size_t)(b * SS + s0 + r0)) * HH + tx * 4) =
                make_float4(v0.x * m0, v1.x * m0, v2.x * m0, v3.x * m0);
            *(float4*)(qs_buf + ((size_t)(b * SS + s0 + r1)) * HH + tx * 4) =
                make_float4(v0.y * m1, v1.y * m1, v2.y * m1, v3.y * m1);
        } else {
            int h0 = (tx - 4) * 4;
            float k00 = v0.x * m0, k01 = v1.x * m0, k02 = v2.x * m0, k03 = v3.x * m0;
            float k10 = v0.y * m1, k11 = v1.y * m1, k12 = v2.y * m1, k13 = v3.y * m1;
            ks_dup[r0][h0 + 0] = pack2(k00, k00);
            ks_dup[r0][h0 + 1] = pack2(k01, k01);
            ks_dup[r0][h0 + 2] = pack2(k02, k02);
            ks_dup[r0][h0 + 3] = pack2(k03, k03);
            ks_dup[r1][h0 + 0] = pack2(k10, k10);
            ks_dup[r1][h0 + 1] = pack2(k11, k11);
            ks_dup[r1][h0 + 2] = pack2(k12, k12);
            ks_dup[r1][h0 + 3] = pack2(k13, k13);
        }
    }
    __syncthreads();

    // ---- phase B: g + hbar accumulation (thread owns e = tid*4 .. +3) ----
    u64 g[16][2];
#pragma unroll
    for (int h = 0; h < 16; h++) { g[h][0] = 0ull; g[h][1] = 0ull; }
    u64 hb0 = 0ull, hb1 = 0ull;

    const char* hrow = (const char*)(Abase + tid * 4);
#pragma unroll 2
    for (int r = 0; r < MT; r++) {
        ulonglong2 hv = *(const ulonglong2*)(hrow + (size_t)r * (HIDD * 4));
        u64 md = m_dup[r];
        hb0 = ffma2(hv.x, md, hb0);
        hb1 = ffma2(hv.y, md, hb1);
#pragma unroll
        for (int hh = 0; hh < 8; hh++) {
            ulonglong2 kp = *(const ulonglong2*)&ks_dup[r][hh * 2];
            g[2 * hh + 0][0] = ffma2(hv.x, kp.x, g[2 * hh + 0][0]);
            g[2 * hh + 0][1] = ffma2(hv.y, kp.x, g[2 * hh + 0][1]);
            g[2 * hh + 1][0] = ffma2(hv.x, kp.y, g[2 * hh + 1][0]);
            g[2 * hh + 1][1] = ffma2(hv.y, kp.y, g[2 * hh + 1][1]);
        }
    }

#pragma unroll
    for (int h = 0; h < 16; h++) {
        float2 x = unpack2(g[h][0]), y = unpack2(g[h][1]);
        *(float4*)(g_scratch + ((size_t)tile * HH + h) * HIDD + tid * 4) =
            make_float4(x.x, x.y, y.x, y.y);
    }
    {
        float2 x = unpack2(hb0), y = unpack2(hb1);
        *(float4*)(hbar_scratch + (size_t)tile * HIDD + tid * 4) =
            make_float4(x.x, x.y, y.x, y.y);
    }
}

// ============================================================
// K2a: reduce hbar partials per batch + invlen. grid 8, block 1024
// ============================================================
__global__ void k2a_hbar(const float* __restrict__ mask) {
    int b = blockIdx.x;
    int e = threadIdx.x;
    float a[8];
#pragma unroll
    for (int j = 0; j < 8; j++) a[j] = 0.f;
    const float* base = hbar_scratch + (size_t)b * K1_CHUNKS * HIDD + e;
#pragma unroll
    for (int c = 0; c < K1_CHUNKS; c += 8)
#pragma unroll
        for (int j = 0; j < 8; j++) a[j] += base[(size_t)(c + j) * HIDD];
    hbar_final[b * HIDD + e] =
        ((a[0] + a[1]) + (a[2] + a[3])) + ((a[4] + a[5]) + (a[6] + a[7]));

    __shared__ float red[1024];
    float s = 0.f;
    for (int i = threadIdx.x; i < SS; i += 1024) s += mask[(size_t)b * SS + i];
    red[threadIdx.x] = s;
    __syncthreads();
    for (int st = 512; st > 0; st >>= 1) {
        if (threadIdx.x < st) red[threadIdx.x] += red[threadIdx.x + st];
        __syncthreads();
    }
    if (threadIdx.x == 0) invlen_buf[b] = 1.f / red[0];
}

// ============================================================
// K2: per (b,h): reduce g partials, then kv/mv = (g|hbar) . Wv rows
// grid 128, block 1024
// ============================================================
__global__ void __launch_bounds__(1024)
k2_kvmv(const float* __restrict__ Wv) {
    int b = blockIdx.x >> 4, h = blockIdx.x & 15;
    __shared__ float gsum[HIDD];
    __shared__ float hsum[HIDD];

    int e = threadIdx.x;
    {
        float a[8];
#pragma unroll
        for (int j = 0; j < 8; j++) a[j] = 0.f;
        const float* base = g_scratch + (((size_t)b * K1_CHUNKS) * HH + h) * HIDD + e;
#pragma unroll
        for (int c = 0; c < K1_CHUNKS; c += 8)
#pragma unroll
            for (int j = 0; j < 8; j++) a[j] += base[(size_t)(c + j) * HH * HIDD];
        gsum[e] = ((a[0] + a[1]) + (a[2] + a[3])) + ((a[4] + a[5]) + (a[6] + a[7]));
        hsum[e] = hbar_final[b * HIDD + e];
    }
    __syncthreads();

    int w = threadIdx.x >> 5, l = threadIdx.x & 31;
#pragma unroll
    for (int dd = 0; dd < 2; dd++) {
        int d = w * 2 + dd;
        const float* wvrow = Wv + (size_t)(h * DHH + d) * HIDD;
        float ak = 0.f, am = 0.f;
#pragma unroll 8
        for (int e2 = l; e2 < HIDD; e2 += 32) {
            float wv = __ldg(wvrow + e2);
            ak += gsum[e2] * wv;
            am += hsum[e2] * wv;
        }
#pragma unroll
        for (int off = 16; off > 0; off >>= 1) {
            ak += __shfl_xor_sync(0xffffffffu, ak, off);
            am += __shfl_xor_sync(0xffffffffu, am, off);
        }
        if (l == 0) {
            kv_buf[((b * HH + h) << 6) + d] = ak;
            mv_buf[((b * HH + h) << 6) + d] = am;
        }
    }
}

// ============================================================
// K3: out[b][s][h*64+d] = (qs[b,s,h]*mv[b,h,d] + kv[b,h,d]) * invlen[b]
// grid 8192 (4 rows each), block 256
// ============================================================
__global__ void k3_out(float* __restrict__ out) {
    int row0 = blockIdx.x << 2;
    int b = row0 >> 12;
    int t = threadIdx.x;
    int h = t >> 4;
    int d = (t & 15) << 2;
    float4 mv4 = *(const float4*)(mv_buf + ((b * HH + h) << 6) + d);
    float4 kv4 = *(const float4*)(kv_buf + ((b * HH + h) << 6) + d);
    float il = invlen_buf[b];
    float4 mvi = make_float4(mv4.x * il, mv4.y * il, mv4.z * il, mv4.w * il);
    float4 kvi = make_float4(kv4.x * il, kv4.y * il, kv4.z * il, kv4.w * il);
#pragma unroll
    for (int rr = 0; rr < 4; rr++) {
        int row = row0 + rr;
        float qsv = __ldg(qs_buf + (size_t)row * HH + h);
        float4 o;
        o.x = qsv * mvi.x + kvi.x;
        o.y = qsv * mvi.y + kvi.y;
        o.z = qsv * mvi.z + kvi.z;
        o.w = qsv * mvi.w + kvi.w;
        ((float4*)out)[(size_t)row * 256 + t] = o;
    }
}

// ============================================================
extern "C" void kernel_launch(void* const* d_in, const int* in_sizes, int n_in,
                              void* d_out, int out_size) {
    const float* hidden = (const float*)d_in[0];
    const float* mask   = (const float*)d_in[1];
    const float* Wq     = (const float*)d_in[2];
    const float* Wk     = (const float*)d_in[3];
    const float* Wv     = (const float*)d_in[4];
    const float* aw     = (const float*)d_in[5];
    float* out = (float*)d_out;

    cudaFuncSetAttribute(k1_main, cudaFuncAttributeMaxDynamicSharedMemorySize, SM_TOT);

    k0_weff<<<32, 256>>>(Wq, Wk, aw);
    k1_main<<<K1_BLOCKS, 256, SM_TOT>>>(hidden, mask);
    k2a_hbar<<<BB, 1024>>>(mask);
    k2_kvmv<<<BB * HH, 1024>>>(Wv);
    k3_out<<<BB * SS / 4, 256>>>(out);
}

// round 5
// speedup vs baseline: 1.3551x; 1.3551x over previous
#include <cuda_runtime.h>
#include <cstdint>

#define BB   8
#define SS   4096
#define HIDD 1024
#define HH   16
#define DHH  64

#define MT        128                 // rows per k1 block
#define KC        32                  // k-chunk
#define NC        (HIDD / KC)         // 32 chunks
#define K1_CHUNKS 32                  // tiles per batch (SS/MT)
#define K1_BLOCKS (BB * K1_CHUNKS)    // 256

// ---------- static scratch (no allocations allowed) ----------
__device__ float g_scratch[(size_t)K1_BLOCKS * HH * HIDD]; // 16.8 MB
__device__ float hbar_scratch[(size_t)K1_BLOCKS * HIDD];   // 1 MB
__device__ float wqk_eff[2 * HH * HIDD];                   // [vec][e], vec<16: q, >=16: k
__device__ float qs_buf[(size_t)BB * SS * HH];             // 2 MB
__device__ float hbar_final[BB * HIDD];
__device__ float kv_buf[BB * HH * DHH];
__device__ float mv_buf[BB * HH * DHH];
__device__ float invlen_buf[BB];

typedef unsigned long long u64;

__device__ __forceinline__ u64 ffma2(u64 a, u64 b, u64 c) {
    u64 d;
    asm("fma.rn.f32x2 %0, %1, %2, %3;" : "=l"(d) : "l"(a), "l"(b), "l"(c));
    return d;
}
__device__ __forceinline__ u64 pack2(float x, float y) {
    u64 r; asm("mov.b64 %0, {%1,%2};" : "=l"(r) : "f"(x), "f"(y)); return r;
}
__device__ __forceinline__ float2 unpack2(u64 v) {
    float2 r; asm("mov.b64 {%0,%1}, %2;" : "=f"(r.x), "=f"(r.y) : "l"(v)); return r;
}

// ---------- dynamic smem layout for k1 ----------
// As: [2][MT][32] u64 (A duplicated (a,a), k XOR-swizzled by ((r>>2)&3)<<3)
// Bs: [2][KC][32] float (R3 layout, conflict-free)
// ks_dup: [MT][16] u64 ; m_dup: [MT] u64 ; m_sh: [MT] float
#define SM_AS   0
#define SM_BS   65536
#define SM_KS   (SM_BS + 8192)       // 73728
#define SM_MD   (SM_KS + 16384)      // 90112
#define SM_MS   (SM_MD + 1024)       // 91136
#define SM_TOT  (SM_MS + 512)        // 91648 B  (occ 2 -> 183 KB < 228 KB)

// ============================================================
// K0: wqk_eff[ch*16+h][e] = sum_d aw[h][d] * W[(h*64+d)][e]
// ============================================================
__global__ void k0_weff(const float* __restrict__ Wq,
                        const float* __restrict__ Wk,
                        const float* __restrict__ aw) {
    int ch = blockIdx.x >> 4, h = blockIdx.x & 15;
    const float* W = ch ? Wk : Wq;
    __shared__ float a_sh[DHH];
    if (threadIdx.x < DHH) a_sh[threadIdx.x] = aw[h * DHH + threadIdx.x];
    __syncthreads();
    for (int e = threadIdx.x; e < HIDD; e += blockDim.x) {
        float acc = 0.f;
#pragma unroll 8
        for (int d = 0; d < DHH; d++)
            acc += a_sh[d] * W[(size_t)(h * DHH + d) * HIDD + e];
        wqk_eff[(ch * HH + h) * HIDD + e] = acc;
    }
}

// ============================================================
// K1: 128-row tile, 256 threads, occ 2, double-buffered (1 sync/chunk).
// Inner loop per 2 k's: 4 LDS.128 (dup'd A, swizzled, conflict-free) +
// 4 LDS.64 (B, conflict-free) + 16 FFMA2  ->  FMA-pipe-bound.
// Phase B: g/hbar outer products (as R3).
// ============================================================
__global__ void __launch_bounds__(256, 2)
k1_main(const float* __restrict__ hidden, const float* __restrict__ mask) {
    extern __shared__ char smem_raw[];
    u64   (*As)[MT][32]   = reinterpret_cast<u64 (*)[MT][32]>(smem_raw + SM_AS);
    float (*Bs)[KC][32]   = reinterpret_cast<float (*)[KC][32]>(smem_raw + SM_BS);
    u64   (*ks_dup)[16]   = reinterpret_cast<u64 (*)[16]>(smem_raw + SM_KS);
    u64*  m_dup           = reinterpret_cast<u64*>(smem_raw + SM_MD);
    float* m_sh           = reinterpret_cast<float*>(smem_raw + SM_MS);

    const int tile = blockIdx.x;
    const int b = tile >> 5;
    const int s0 = (tile & 31) * MT;
    const int tid = threadIdx.x;
    const int tx = tid & 7;              // col-group (4 cols)
    const int ty = tid >> 3;             // row-group (rows ty*4 .. ty*4+3)
    const int sA = (ty & 3) << 3;        // load-side k swizzle (bits 3-4)

    const float* Abase = hidden + ((size_t)b * SS + s0) * HIDD;

    if (tid < MT) {
        float m = mask[(size_t)b * SS + s0 + tid];
        m_sh[tid] = m;
        m_dup[tid] = pack2(m, m);
    }

    // acc[row i][colpair j]: row ty*4+i, cols (tx*4+2j, tx*4+2j+1)
    u64 acc[4][2];
#pragma unroll
    for (int i = 0; i < 4; i++) { acc[i][0] = 0ull; acc[i][1] = 0ull; }

    const int sv  = tid & 31;            // B staging: col
    const int skq = tid >> 5;            // B staging: k-quad

    // staging decode (constant per thread)
    int sr[4], srw[4];
#pragma unroll
    for (int i = 0; i < 4; i++) {
        int idx = tid + i * 256;
        sr[i]  = idx >> 3;                          // row
        srw[i] = ((idx & 7) * 4) ^ (((sr[i] >> 2) & 3) << 3);  // swizzled k-quad start
    }

    float4 aR[4];
    float4 bR;

    // ---- prologue: stage chunk 0 into buffer 0 ----
#pragma unroll
    for (int i = 0; i < 4; i++) {
        int idx = tid + i * 256;
        aR[i] = *(const float4*)(Abase + (size_t)(idx >> 3) * HIDD + (idx & 7) * 4);
    }
    bR = *(const float4*)(wqk_eff + (size_t)sv * HIDD + skq * 4);
#pragma unroll
    for (int i = 0; i < 4; i++) {
        ulonglong2 lo, hi;
        lo.x = pack2(aR[i].x, aR[i].x); lo.y = pack2(aR[i].y, aR[i].y);
        hi.x = pack2(aR[i].z, aR[i].z); hi.y = pack2(aR[i].w, aR[i].w);
        *(ulonglong2*)&As[0][sr[i]][srw[i]]     = lo;
        *(ulonglong2*)&As[0][sr[i]][srw[i] + 2] = hi;
    }
    Bs[0][skq * 4 + 0][sv] = bR.x;
    Bs[0][skq * 4 + 1][sv] = bR.y;
    Bs[0][skq * 4 + 2][sv] = bR.z;
    Bs[0][skq * 4 + 3][sv] = bR.w;
    __syncthreads();

    // ---- main loop: double-buffered, 1 sync per chunk ----
#pragma unroll 1
    for (int c = 0; c < NC; c++) {
        const int cur = c & 1, nxt = cur ^ 1;
        if (c + 1 < NC) {
            int k0 = (c + 1) * KC;
#pragma unroll
            for (int i = 0; i < 4; i++) {
                int idx = tid + i * 256;
                aR[i] = *(const float4*)(Abase + (size_t)(idx >> 3) * HIDD + k0 + (idx & 7) * 4);
            }
            bR = *(const float4*)(wqk_eff + (size_t)sv * HIDD + k0 + skq * 4);
        }
#pragma unroll
        for (int k = 0; k < KC; k += 2) {
            const int kk = k ^ sA;
            ulonglong2 a0 = *(const ulonglong2*)&As[cur][ty * 4 + 0][kk];
            ulonglong2 a1 = *(const ulonglong2*)&As[cur][ty * 4 + 1][kk];
            ulonglong2 a2 = *(const ulonglong2*)&As[cur][ty * 4 + 2][kk];
            ulonglong2 a3 = *(const ulonglong2*)&As[cur][ty * 4 + 3][kk];
            u64 b00 = *(const u64*)&Bs[cur][k][tx * 4];
            u64 b01 = *(const u64*)&Bs[cur][k][tx * 4 + 2];
            u64 b10 = *(const u64*)&Bs[cur][k + 1][tx * 4];
            u64 b11 = *(const u64*)&Bs[cur][k + 1][tx * 4 + 2];
            acc[0][0] = ffma2(a0.x, b00, acc[0][0]); acc[0][1] = ffma2(a0.x, b01, acc[0][1]);
            acc[1][0] = ffma2(a1.x, b00, acc[1][0]); acc[1][1] = ffma2(a1.x, b01, acc[1][1]);
            acc[2][0] = ffma2(a2.x, b00, acc[2][0]); acc[2][1] = ffma2(a2.x, b01, acc[2][1]);
            acc[3][0] = ffma2(a3.x, b00, acc[3][0]); acc[3][1] = ffma2(a3.x, b01, acc[3][1]);
            acc[0][0] = ffma2(a0.y, b10, acc[0][0]); acc[0][1] = ffma2(a0.y, b11, acc[0][1]);
            acc[1][0] = ffma2(a1.y, b10, acc[1][0]); acc[1][1] = ffma2(a1.y, b11, acc[1][1]);
            acc[2][0] = ffma2(a2.y, b10, acc[2][0]); acc[2][1] = ffma2(a2.y, b11, acc[2][1]);
            acc[3][0] = ffma2(a3.y, b10, acc[3][0]); acc[3][1] = ffma2(a3.y, b11, acc[3][1]);
        }
        if (c + 1 < NC) {
#pragma unroll
            for (int i = 0; i < 4; i++) {
                ulonglong2 lo, hi;
                lo.x = pack2(aR[i].x, aR[i].x); lo.y = pack2(aR[i].y, aR[i].y);
                hi.x = pack2(aR[i].z, aR[i].z); hi.y = pack2(aR[i].w, aR[i].w);
                *(ulonglong2*)&As[nxt][sr[i]][srw[i]]     = lo;
                *(ulonglong2*)&As[nxt][sr[i]][srw[i] + 2] = hi;
            }
            Bs[nxt][skq * 4 + 0][sv] = bR.x;
            Bs[nxt][skq * 4 + 1][sv] = bR.y;
            Bs[nxt][skq * 4 + 2][sv] = bR.z;
            Bs[nxt][skq * 4 + 3][sv] = bR.w;
        }
        __syncthreads();
    }

    // ---- epilogue A: mask, store qs (cols 0..15) or stage ks (cols 16..31) ----
#pragma unroll
    for (int i = 0; i < 4; i++) {
        int r = ty * 4 + i;
        float m = m_sh[r];
        float2 v01 = unpack2(acc[i][0]);
        float2 v23 = unpack2(acc[i][1]);
        float c0 = v01.x * m, c1 = v01.y * m, c2 = v23.x * m, c3 = v23.y * m;
        if (tx < 4) {
            *(float4*)(qs_buf + ((size_t)(b * SS + s0 + r)) * HH + tx * 4) =
                make_float4(c0, c1, c2, c3);
        } else {
            int h0 = tx * 4 - 16;
            ks_dup[r][h0 + 0] = pack2(c0, c0);
            ks_dup[r][h0 + 1] = pack2(c1, c1);
            ks_dup[r][h0 + 2] = pack2(c2, c2);
            ks_dup[r][h0 + 3] = pack2(c3, c3);
        }
    }
    __syncthreads();

    // ---- phase B: g + hbar accumulation (thread owns e = tid*4 .. +3) ----
    u64 g[16][2];
#pragma unroll
    for (int h = 0; h < 16; h++) { g[h][0] = 0ull; g[h][1] = 0ull; }
    u64 hb0 = 0ull, hb1 = 0ull;

    const char* hrow = (const char*)(Abase + tid * 4);
#pragma unroll 2
    for (int r = 0; r < MT; r++) {
        ulonglong2 hv = *(const ulonglong2*)(hrow + (size_t)r * (HIDD * 4));
        u64 md = m_dup[r];
        hb0 = ffma2(hv.x, md, hb0);
        hb1 = ffma2(hv.y, md, hb1);
#pragma unroll
        for (int hh = 0; hh < 8; hh++) {
            ulonglong2 kp = *(const ulonglong2*)&ks_dup[r][hh * 2];
            g[2 * hh + 0][0] = ffma2(hv.x, kp.x, g[2 * hh + 0][0]);
            g[2 * hh + 0][1] = ffma2(hv.y, kp.x, g[2 * hh + 0][1]);
            g[2 * hh + 1][0] = ffma2(hv.x, kp.y, g[2 * hh + 1][0]);
            g[2 * hh + 1][1] = ffma2(hv.y, kp.y, g[2 * hh + 1][1]);
        }
    }

#pragma unroll
    for (int h = 0; h < 16; h++) {
        float2 x = unpack2(g[h][0]), y = unpack2(g[h][1]);
        *(float4*)(g_scratch + ((size_t)tile * HH + h) * HIDD + tid * 4) =
            make_float4(x.x, x.y, y.x, y.y);
    }
    {
        float2 x = unpack2(hb0), y = unpack2(hb1);
        *(float4*)(hbar_scratch + (size_t)tile * HIDD + tid * 4) =
            make_float4(x.x, x.y, y.x, y.y);
    }
}

// ============================================================
// K2a: reduce hbar partials per batch + invlen. grid 8, block 1024
// ============================================================
__global__ void k2a_hbar(const float* __restrict__ mask) {
    int b = blockIdx.x;
    int e = threadIdx.x;
    float a[8];
#pragma unroll
    for (int j = 0; j < 8; j++) a[j] = 0.f;
    const float* base = hbar_scratch + (size_t)b * K1_CHUNKS * HIDD + e;
#pragma unroll
    for (int c = 0; c < K1_CHUNKS; c += 8)
#pragma unroll
        for (int j = 0; j < 8; j++) a[j] += base[(size_t)(c + j) * HIDD];
    hbar_final[b * HIDD + e] =
        ((a[0] + a[1]) + (a[2] + a[3])) + ((a[4] + a[5]) + (a[6] + a[7]));

    __shared__ float red[1024];
    float s = 0.f;
    for (int i = threadIdx.x; i < SS; i += 1024) s += mask[(size_t)b * SS + i];
    red[threadIdx.x] = s;
    __syncthreads();
    for (int st = 512; st > 0; st >>= 1) {
        if (threadIdx.x < st) red[threadIdx.x] += red[threadIdx.x + st];
        __syncthreads();
    }
    if (threadIdx.x == 0) invlen_buf[b] = 1.f / red[0];
}

// ============================================================
// K2: per (b,h): reduce g partials, then kv/mv = (g|hbar) . Wv rows
// grid 128, block 1024
// ============================================================
__global__ void __launch_bounds__(1024)
k2_kvmv(const float* __restrict__ Wv) {
    int b = blockIdx.x >> 4, h = blockIdx.x & 15;
    __shared__ float gsum[HIDD];
    __shared__ float hsum[HIDD];

    int e = threadIdx.x;
    {
        float a[8];
#pragma unroll
        for (int j = 0; j < 8; j++) a[j] = 0.f;
        const float* base = g_scratch + (((size_t)b * K1_CHUNKS) * HH + h) * HIDD + e;
#pragma unroll
        for (int c = 0; c < K1_CHUNKS; c += 8)
#pragma unroll
            for (int j = 0; j < 8; j++) a[j] += base[(size_t)(c + j) * HH * HIDD];
        gsum[e] = ((a[0] + a[1]) + (a[2] + a[3])) + ((a[4] + a[5]) + (a[6] + a[7]));
        hsum[e] = hbar_final[b * HIDD + e];
    }
    __syncthreads();

    int w = threadIdx.x >> 5, l = threadIdx.x & 31;
#pragma unroll
    for (int dd = 0; dd < 2; dd++) {
        int d = w * 2 + dd;
        const float* wvrow = Wv + (size_t)(h * DHH + d) * HIDD;
        float ak = 0.f, am = 0.f;
#pragma unroll 8
        for (int e2 = l; e2 < HIDD; e2 += 32) {
            float wv = __ldg(wvrow + e2);
            ak += gsum[e2] * wv;
            am += hsum[e2] * wv;
        }
#pragma unroll
        for (int off = 16; off > 0; off >>= 1) {
            ak += __shfl_xor_sync(0xffffffffu, ak, off);
            am += __shfl_xor_sync(0xffffffffu, am, off);
        }
        if (l == 0) {
            kv_buf[((b * HH + h) << 6) + d] = ak;
            mv_buf[((b * HH + h) << 6) + d] = am;
        }
    }
}

// ============================================================
// K3: out[b][s][h*64+d] = (qs[b,s,h]*mv[b,h,d] + kv[b,h,d]) * invlen[b]
// grid 8192 (4 rows each), block 256
// ============================================================
__global__ void k3_out(float* __restrict__ out) {
    int row0 = blockIdx.x << 2;
    int b = row0 >> 12;
    int t = threadIdx.x;
    int h = t >> 4;
    int d = (t & 15) << 2;
    float4 mv4 = *(const float4*)(mv_buf + ((b * HH + h) << 6) + d);
    float4 kv4 = *(const float4*)(kv_buf + ((b * HH + h) << 6) + d);
    float il = invlen_buf[b];
    float4 mvi = make_float4(mv4.x * il, mv4.y * il, mv4.z * il, mv4.w * il);
    float4 kvi = make_float4(kv4.x * il, kv4.y * il, kv4.z * il, kv4.w * il);
#pragma unroll
    for (int rr = 0; rr < 4; rr++) {
        int row = row0 + rr;
        float qsv = __ldg(qs_buf + (size_t)row * HH + h);
        float4 o;
        o.x = qsv * mvi.x + kvi.x;
        o.y = qsv * mvi.y + kvi.y;
        o.z = qsv * mvi.z + kvi.z;
        o.w = qsv * mvi.w + kvi.w;
        ((float4*)out)[(size_t)row * 256 + t] = o;
    }
}

// ============================================================
extern "C" void kernel_launch(void* const* d_in, const int* in_sizes, int n_in,
                              void* d_out, int out_size) {
    const float* hidden = (const float*)d_in[0];
    const float* mask   = (const float*)d_in[1];
    const float* Wq     = (const float*)d_in[2];
    const float* Wk     = (const float*)d_in[3];
    const float* Wv     = (const float*)d_in[4];
    const float* aw     = (const float*)d_in[5];
    float* out = (float*)d_out;

    cudaFuncSetAttribute(k1_main, cudaFuncAttributeMaxDynamicSharedMemorySize, SM_TOT);

    k0_weff<<<32, 256>>>(Wq, Wk, aw);
    k1_main<<<K1_BLOCKS, 256, SM_TOT>>>(hidden, mask);
    k2a_hbar<<<BB, 1024>>>(mask);
    k2_kvmv<<<BB * HH, 1024>>>(Wv);
    k3_out<<<BB * SS / 4, 256>>>(out);
}

// round 6
// speedup vs baseline: 1.6610x; 1.2258x over previous
#include <cuda_runtime.h>
#include <cstdint>

#define BB   8
#define SS   4096
#define HIDD 1024
#define HH   16
#define DHH  64

#define MT    128                // rows per tile
#define KC    32                 // k-chunk
#define NC    (HIDD / KC)        // 32
#define TILES 32                 // tiles per batch
#define NBLK  (BB * TILES)       // 256

// ---------- static scratch ----------
__device__ float g_scratch[(size_t)NBLK * HH * HIDD]; // 16.8 MB
__device__ float hbar_scratch[(size_t)NBLK * HIDD];   // 1 MB
__device__ float wqk_eff[2 * HH * HIDD];
__device__ float qs_buf[(size_t)BB * SS * HH];        // 2 MB
__device__ float ks_buf[(size_t)BB * SS * HH];        // 2 MB
__device__ float hbar_final[BB * HIDD];
__device__ float kv_buf[BB * HH * DHH];
__device__ float mv_buf[BB * HH * DHH];
__device__ float invlen_buf[BB];

typedef unsigned long long u64;

__device__ __forceinline__ u64 ffma2(u64 a, u64 b, u64 c) {
    u64 d;
    asm("fma.rn.f32x2 %0, %1, %2, %3;" : "=l"(d) : "l"(a), "l"(b), "l"(c));
    return d;
}
__device__ __forceinline__ u64 pack2(float x, float y) {
    u64 r; asm("mov.b64 %0, {%1,%2};" : "=l"(r) : "f"(x), "f"(y)); return r;
}
__device__ __forceinline__ float2 unpack2(u64 v) {
    float2 r; asm("mov.b64 {%0,%1}, %2;" : "=f"(r.x), "=f"(r.y) : "l"(v)); return r;
}

// ============================================================
// K0: wqk_eff[ch*16+h][e] = sum_d aw[h][d] * W[(h*64+d)][e]
// ============================================================
__global__ void k0_weff(const float* __restrict__ Wq,
                        const float* __restrict__ Wk,
                        const float* __restrict__ aw) {
    int ch = blockIdx.x >> 4, h = blockIdx.x & 15;
    const float* W = ch ? Wk : Wq;
    __shared__ float a_sh[DHH];
    if (threadIdx.x < DHH) a_sh[threadIdx.x] = aw[h * DHH + threadIdx.x];
    __syncthreads();
    for (int e = threadIdx.x; e < HIDD; e += blockDim.x) {
        float acc = 0.f;
#pragma unroll 8
        for (int d = 0; d < DHH; d++)
            acc += a_sh[d] * W[(size_t)(h * DHH + d) * HIDD + e];
        wqk_eff[(ch * HH + h) * HIDD + e] = acc;
    }
}

// ============================================================
// K1a: GEMM C[128x32] = tile x wqk_eff^T, 128 threads, tile 8x4.
// k-paired FFMA2 accumulators (lo=even k, hi=odd k; summed at epilogue).
// Thread (tx=tid&7, ty=tid>>3): rows ty+16i (i<8), cols tx+8j (j<4).
// Inner per k-pair: 8 LDS.64 A + 4 LDS.64 B + 32 FFMA2 (~1.5 B/FMA charged).
// Writes qs (cols 0..15) and ks (cols 16..31), masked, to global.
// ============================================================
__global__ void __launch_bounds__(128, 3)
k1a_gemm(const float* __restrict__ hidden, const float* __restrict__ mask) {
    __shared__ float As[MT][34];     // stride 34: 4 consec rows -> banks +2 apart
    __shared__ float Bt[32][36];     // stride 36: cols tx+8j -> banks 4*tx

    const int tile = blockIdx.x;
    const int b = tile >> 5;
    const int s0 = (tile & 31) * MT;
    const int tid = threadIdx.x;
    const int tx = tid & 7;
    const int ty = tid >> 3;         // 0..15

    const float* Ab = hidden + ((size_t)b * SS + s0) * HIDD;

    u64 acc[8][4];
#pragma unroll
    for (int i = 0; i < 8; i++)
#pragma unroll
        for (int j = 0; j < 4; j++) acc[i][j] = 0ull;

    float4 aR[8];
    float  bR[8];

    // ---- prologue: load + stage chunk 0 ----
#pragma unroll
    for (int i = 0; i < 8; i++) {
        int idx = tid + i * 128;
        aR[i] = *(const float4*)(Ab + (size_t)(idx >> 3) * HIDD + (idx & 7) * 4);
    }
#pragma unroll
    for (int p = 0; p < 8; p++) {
        int idx = tid + p * 128;
        bR[p] = wqk_eff[(size_t)(idx >> 5) * HIDD + (idx & 31)];
    }
#pragma unroll
    for (int i = 0; i < 8; i++) {
        int idx = tid + i * 128;
        int r = idx >> 3, kq = (idx & 7) * 4;
        *(float2*)&As[r][kq]     = make_float2(aR[i].x, aR[i].y);
        *(float2*)&As[r][kq + 2] = make_float2(aR[i].z, aR[i].w);
    }
#pragma unroll
    for (int p = 0; p < 8; p++) {
        int idx = tid + p * 128;
        Bt[idx >> 5][idx & 31] = bR[p];
    }
    __syncthreads();

    // ---- main loop ----
#pragma unroll 1
    for (int c = 0; c < NC; c++) {
        if (c + 1 < NC) {
            int k0 = (c + 1) * KC;
#pragma unroll
            for (int i = 0; i < 8; i++) {
                int idx = tid + i * 128;
                aR[i] = *(const float4*)(Ab + (size_t)(idx >> 3) * HIDD + k0 + (idx & 7) * 4);
            }
#pragma unroll
            for (int p = 0; p < 8; p++) {
                int idx = tid + p * 128;
                bR[p] = wqk_eff[(size_t)(idx >> 5) * HIDD + k0 + (idx & 31)];
            }
        }
#pragma unroll
        for (int k = 0; k < KC; k += 2) {
            u64 a[8], bv[4];
#pragma unroll
            for (int i = 0; i < 8; i++) a[i] = *(const u64*)&As[ty + 16 * i][k];
#pragma unroll
            for (int j = 0; j < 4; j++) bv[j] = *(const u64*)&Bt[tx + 8 * j][k];
#pragma unroll
            for (int i = 0; i < 8; i++) {
                acc[i][0] = ffma2(a[i], bv[0], acc[i][0]);
                acc[i][1] = ffma2(a[i], bv[1], acc[i][1]);
                acc[i][2] = ffma2(a[i], bv[2], acc[i][2]);
                acc[i][3] = ffma2(a[i], bv[3], acc[i][3]);
            }
        }
        __syncthreads();
        if (c + 1 < NC) {
#pragma unroll
            for (int i = 0; i < 8; i++) {
                int idx = tid + i * 128;
                int r = idx >> 3, kq = (idx & 7) * 4;
                *(float2*)&As[r][kq]     = make_float2(aR[i].x, aR[i].y);
                *(float2*)&As[r][kq + 2] = make_float2(aR[i].z, aR[i].w);
            }
#pragma unroll
            for (int p = 0; p < 8; p++) {
                int idx = tid + p * 128;
                Bt[idx >> 5][idx & 31] = bR[p];
            }
            __syncthreads();
        }
    }

    // ---- epilogue: sum k-pair lanes, apply mask, write qs/ks ----
#pragma unroll
    for (int i = 0; i < 8; i++) {
        int row = ty + 16 * i;
        float m = mask[(size_t)b * SS + s0 + row];
        float2 f0 = unpack2(acc[i][0]);
        float2 f1 = unpack2(acc[i][1]);
        float2 f2 = unpack2(acc[i][2]);
        float2 f3 = unpack2(acc[i][3]);
        float v0 = (f0.x + f0.y) * m;   // col tx      (q)
        float v1 = (f1.x + f1.y) * m;   // col tx+8    (q)
        float v2 = (f2.x + f2.y) * m;   // col tx+16   (k)
        float v3 = (f3.x + f3.y) * m;   // col tx+24   (k)
        size_t rb = ((size_t)(b * SS + s0 + row)) * HH;
        qs_buf[rb + tx]     = v0;
        qs_buf[rb + tx + 8] = v1;
        ks_buf[rb + tx]     = v2;
        ks_buf[rb + tx + 8] = v3;
    }
}

// ============================================================
// K1b: g[h][e] += ks[s][h]*H[s][e] ; hbar[e] += m[s]*H[s][e]
// 256 threads, thread owns e = tid*4..+3; 4-row front-batched loads.
// ============================================================
__global__ void __launch_bounds__(256, 2)
k1b_accum(const float* __restrict__ hidden, const float* __restrict__ mask) {
    __shared__ u64 ks_dup[MT][16];
    __shared__ u64 m_dup[MT];

    const int tile = blockIdx.x;
    const int b = tile >> 5;
    const int s0 = (tile & 31) * MT;
    const int tid = threadIdx.x;
    const float* Ab = hidden + ((size_t)b * SS + s0) * HIDD;

#pragma unroll
    for (int p = 0; p < 8; p++) {
        int idx = tid + 256 * p;            // 0..2047
        int r = idx >> 4, h = idx & 15;
        float v = ks_buf[((size_t)(b * SS + s0 + r)) * HH + h];
        ks_dup[r][h] = pack2(v, v);
    }
    if (tid < MT) {
        float m = mask[(size_t)b * SS + s0 + tid];
        m_dup[tid] = pack2(m, m);
    }
    __syncthreads();

    u64 g[16][2];
#pragma unroll
    for (int h = 0; h < 16; h++) { g[h][0] = 0ull; g[h][1] = 0ull; }
    u64 hb0 = 0ull, hb1 = 0ull;

    const char* hrow = (const char*)(Ab + tid * 4);
#pragma unroll 1
    for (int r0 = 0; r0 < MT; r0 += 4) {
        ulonglong2 hv[4];
#pragma unroll
        for (int u = 0; u < 4; u++)
            hv[u] = *(const ulonglong2*)(hrow + (size_t)(r0 + u) * (HIDD * 4));
#pragma unroll
        for (int u = 0; u < 4; u++) {
            u64 md = m_dup[r0 + u];
            hb0 = ffma2(hv[u].x, md, hb0);
            hb1 = ffma2(hv[u].y, md, hb1);
#pragma unroll
            for (int hh = 0; hh < 8; hh++) {
                ulonglong2 kp = *(const ulonglong2*)&ks_dup[r0 + u][hh * 2];
                g[2 * hh + 0][0] = ffma2(hv[u].x, kp.x, g[2 * hh + 0][0]);
                g[2 * hh + 0][1] = ffma2(hv[u].y, kp.x, g[2 * hh + 0][1]);
                g[2 * hh + 1][0] = ffma2(hv[u].x, kp.y, g[2 * hh + 1][0]);
                g[2 * hh + 1][1] = ffma2(hv[u].y, kp.y, g[2 * hh + 1][1]);
            }
        }
    }

#pragma unroll
    for (int h = 0; h < 16; h++) {
        float2 x = unpack2(g[h][0]), y = unpack2(g[h][1]);
        *(float4*)(g_scratch + ((size_t)tile * HH + h) * HIDD + tid * 4) =
            make_float4(x.x, x.y, y.x, y.y);
    }
    {
        float2 x = unpack2(hb0), y = unpack2(hb1);
        *(float4*)(hbar_scratch + (size_t)tile * HIDD + tid * 4) =
            make_float4(x.x, x.y, y.x, y.y);
    }
}

// ============================================================
// K2a: reduce hbar partials per batch + invlen. grid 8, block 1024
// ============================================================
__global__ void k2a_hbar(const float* __restrict__ mask) {
    int b = blockIdx.x;
    int e = threadIdx.x;
    float a[8];
#pragma unroll
    for (int j = 0; j < 8; j++) a[j] = 0.f;
    const float* base = hbar_scratch + (size_t)b * TILES * HIDD + e;
#pragma unroll
    for (int c = 0; c < TILES; c += 8)
#pragma unroll
        for (int j = 0; j < 8; j++) a[j] += base[(size_t)(c + j) * HIDD];
    hbar_final[b * HIDD + e] =
        ((a[0] + a[1]) + (a[2] + a[3])) + ((a[4] + a[5]) + (a[6] + a[7]));

    __shared__ float red[1024];
    float s = 0.f;
    for (int i = threadIdx.x; i < SS; i += 1024) s += mask[(size_t)b * SS + i];
    red[threadIdx.x] = s;
    __syncthreads();
    for (int st = 512; st > 0; st >>= 1) {
        if (threadIdx.x < st) red[threadIdx.x] += red[threadIdx.x + st];
        __syncthreads();
    }
    if (threadIdx.x == 0) invlen_buf[b] = 1.f / red[0];
}

// ============================================================
// K2: per (b,h): reduce g partials, then kv/mv = (g|hbar) . Wv rows
// ============================================================
__global__ void __launch_bounds__(1024)
k2_kvmv(const float* __restrict__ Wv) {
    int b = blockIdx.x >> 4, h = blockIdx.x & 15;
    __shared__ float gsum[HIDD];
    __shared__ float hsum[HIDD];

    int e = threadIdx.x;
    {
        float a[8];
#pragma unroll
        for (int j = 0; j < 8; j++) a[j] = 0.f;
        const float* base = g_scratch + (((size_t)b * TILES) * HH + h) * HIDD + e;
#pragma unroll
        for (int c = 0; c < TILES; c += 8)
#pragma unroll
            for (int j = 0; j < 8; j++) a[j] += base[(size_t)(c + j) * HH * HIDD];
        gsum[e] = ((a[0] + a[1]) + (a[2] + a[3])) + ((a[4] + a[5]) + (a[6] + a[7]));
        hsum[e] = hbar_final[b * HIDD + e];
    }
    __syncthreads();

    int w = threadIdx.x >> 5, l = threadIdx.x & 31;
#pragma unroll
    for (int dd = 0; dd < 2; dd++) {
        int d = w * 2 + dd;
        const float* wvrow = Wv + (size_t)(h * DHH + d) * HIDD;
        float ak = 0.f, am = 0.f;
#pragma unroll 8
        for (int e2 = l; e2 < HIDD; e2 += 32) {
            float wv = __ldg(wvrow + e2);
            ak += gsum[e2] * wv;
            am += hsum[e2] * wv;
        }
#pragma unroll
        for (int off = 16; off > 0; off >>= 1) {
            ak += __shfl_xor_sync(0xffffffffu, ak, off);
            am += __shfl_xor_sync(0xffffffffu, am, off);
        }
        if (l == 0) {
            kv_buf[((b * HH + h) << 6) + d] = ak;
            mv_buf[((b * HH + h) << 6) + d] = am;
        }
    }
}

// ============================================================
// K3: out = (qs*mv + kv)*invlen ; 8 rows/block, streaming stores
// ============================================================
__global__ void k3_out(float* __restrict__ out) {
    int row0 = blockIdx.x << 3;
    int b = row0 >> 12;
    int t = threadIdx.x;
    int h = t >> 4;
    int d = (t & 15) << 2;
    float4 mv4 = *(const float4*)(mv_buf + ((b * HH + h) << 6) + d);
    float4 kv4 = *(const float4*)(kv_buf + ((b * HH + h) << 6) + d);
    float il = invlen_buf[b];
    float4 mvi = make_float4(mv4.x * il, mv4.y * il, mv4.z * il, mv4.w * il);
    float4 kvi = make_float4(kv4.x * il, kv4.y * il, kv4.z * il, kv4.w * il);
#pragma unroll
    for (int rr = 0; rr < 8; rr++) {
        int row = row0 + rr;
        float qsv = __ldg(qs_buf + (size_t)row * HH + h);
        float4 o;
        o.x = qsv * mvi.x + kvi.x;
        o.y = qsv * mvi.y + kvi.y;
        o.z = qsv * mvi.z + kvi.z;
        o.w = qsv * mvi.w + kvi.w;
        __stcs(((float4*)out) + (size_t)row * 256 + t, o);
    }
}

// ============================================================
extern "C" void kernel_launch(void* const* d_in, const int* in_sizes, int n_in,
                              void* d_out, int out_size) {
    const float* hidden = (const float*)d_in[0];
    const float* mask   = (const float*)d_in[1];
    const float* Wq     = (const float*)d_in[2];
    const float* Wk     = (const float*)d_in[3];
    const float* Wv     = (const float*)d_in[4];
    const float* aw     = (const float*)d_in[5];
    float* out = (float*)d_out;

    k0_weff<<<32, 256>>>(Wq, Wk, aw);
    k1a_gemm<<<NBLK, 128>>>(hidden, mask);
    k1b_accum<<<NBLK, 256>>>(hidden, mask);
    k2a_hbar<<<BB, 1024>>>(mask);
    k2_kvmv<<<BB * HH, 1024>>>(Wv);
    k3_out<<<BB * SS / 8, 256>>>(out);
}

// round 7
// speedup vs baseline: 1.7319x; 1.0427x over previous
#include <cuda_runtime.h>
#include <cstdint>

#define BB   8
#define SS   4096
#define HIDD 1024
#define HH   16
#define DHH  64

#define MT    128                // rows per tile
#define KC    32                 // k-chunk
#define NC    (HIDD / KC)        // 32
#define TILES 32                 // tiles per batch
#define NBLK  (BB * TILES)       // 256

// ---------- static scratch ----------
__device__ float g_scratch[(size_t)NBLK * HH * HIDD]; // 16.8 MB
__device__ float hbar_scratch[(size_t)NBLK * HIDD];   // 1 MB
__device__ float wqk_eff[2 * HH * HIDD];
__device__ float qs_buf[(size_t)BB * SS * HH];        // 2 MB
__device__ float ks_buf[(size_t)BB * SS * HH];        // 2 MB
__device__ float kv_buf[BB * HH * DHH];
__device__ float mv_buf[BB * HH * DHH];
__device__ float invlen_buf[BB];

typedef unsigned long long u64;

__device__ __forceinline__ u64 ffma2(u64 a, u64 b, u64 c) {
    u64 d;
    asm("fma.rn.f32x2 %0, %1, %2, %3;" : "=l"(d) : "l"(a), "l"(b), "l"(c));
    return d;
}
__device__ __forceinline__ u64 pack2(float x, float y) {
    u64 r; asm("mov.b64 %0, {%1,%2};" : "=l"(r) : "f"(x), "f"(y)); return r;
}
__device__ __forceinline__ float2 unpack2(u64 v) {
    float2 r; asm("mov.b64 {%0,%1}, %2;" : "=f"(r.x), "=f"(r.y) : "l"(v)); return r;
}

// ============================================================
// K0: blocks 0..31: wqk_eff[ch*16+h][e] = sum_d aw[h][d]*W[(h*64+d)][e]
//     blocks 32..39: invlen[b] = 1/sum_s mask[b][s]
// ============================================================
__global__ void k0_weff(const float* __restrict__ Wq,
                        const float* __restrict__ Wk,
                        const float* __restrict__ aw,
                        const float* __restrict__ mask) {
    if (blockIdx.x >= 32) {
        int b = blockIdx.x - 32;
        __shared__ float red[256];
        float s = 0.f;
        for (int i = threadIdx.x; i < SS; i += 256) s += mask[(size_t)b * SS + i];
        red[threadIdx.x] = s;
        __syncthreads();
        for (int st = 128; st > 0; st >>= 1) {
            if (threadIdx.x < st) red[threadIdx.x] += red[threadIdx.x + st];
            __syncthreads();
        }
        if (threadIdx.x == 0) invlen_buf[b] = 1.f / red[0];
        return;
    }
    int ch = blockIdx.x >> 4, h = blockIdx.x & 15;
    const float* W = ch ? Wk : Wq;
    __shared__ float a_sh[DHH];
    if (threadIdx.x < DHH) a_sh[threadIdx.x] = aw[h * DHH + threadIdx.x];
    __syncthreads();
    for (int e = threadIdx.x; e < HIDD; e += blockDim.x) {
        float acc = 0.f;
#pragma unroll 8
        for (int d = 0; d < DHH; d++)
            acc += a_sh[d] * W[(size_t)(h * DHH + d) * HIDD + e];
        wqk_eff[(ch * HH + h) * HIDD + e] = acc;
    }
}

// ============================================================
// K1a: GEMM C[128x32] = tile x wqk_eff^T, 128 threads, tile 8x4,
// k-paired FFMA2 accumulators. (unchanged from R6 — at fp32 FMA floor)
// ============================================================
__global__ void __launch_bounds__(128, 3)
k1a_gemm(const float* __restrict__ hidden, const float* __restrict__ mask) {
    __shared__ float As[MT][34];
    __shared__ float Bt[32][36];

    const int tile = blockIdx.x;
    const int b = tile >> 5;
    const int s0 = (tile & 31) * MT;
    const int tid = threadIdx.x;
    const int tx = tid & 7;
    const int ty = tid >> 3;

    const float* Ab = hidden + ((size_t)b * SS + s0) * HIDD;

    u64 acc[8][4];
#pragma unroll
    for (int i = 0; i < 8; i++)
#pragma unroll
        for (int j = 0; j < 4; j++) acc[i][j] = 0ull;

    float4 aR[8];
    float  bR[8];

#pragma unroll
    for (int i = 0; i < 8; i++) {
        int idx = tid + i * 128;
        aR[i] = *(const float4*)(Ab + (size_t)(idx >> 3) * HIDD + (idx & 7) * 4);
    }
#pragma unroll
    for (int p = 0; p < 8; p++) {
        int idx = tid + p * 128;
        bR[p] = wqk_eff[(size_t)(idx >> 5) * HIDD + (idx & 31)];
    }
#pragma unroll
    for (int i = 0; i < 8; i++) {
        int idx = tid + i * 128;
        int r = idx >> 3, kq = (idx & 7) * 4;
        *(float2*)&As[r][kq]     = make_float2(aR[i].x, aR[i].y);
        *(float2*)&As[r][kq + 2] = make_float2(aR[i].z, aR[i].w);
    }
#pragma unroll
    for (int p = 0; p < 8; p++) {
        int idx = tid + p * 128;
        Bt[idx >> 5][idx & 31] = bR[p];
    }
    __syncthreads();

#pragma unroll 1
    for (int c = 0; c < NC; c++) {
        if (c + 1 < NC) {
            int k0 = (c + 1) * KC;
#pragma unroll
            for (int i = 0; i < 8; i++) {
                int idx = tid + i * 128;
                aR[i] = *(const float4*)(Ab + (size_t)(idx >> 3) * HIDD + k0 + (idx & 7) * 4);
            }
#pragma unroll
            for (int p = 0; p < 8; p++) {
                int idx = tid + p * 128;
                bR[p] = wqk_eff[(size_t)(idx >> 5) * HIDD + k0 + (idx & 31)];
            }
        }
#pragma unroll
        for (int k = 0; k < KC; k += 2) {
            u64 a[8], bv[4];
#pragma unroll
            for (int i = 0; i < 8; i++) a[i] = *(const u64*)&As[ty + 16 * i][k];
#pragma unroll
            for (int j = 0; j < 4; j++) bv[j] = *(const u64*)&Bt[tx + 8 * j][k];
#pragma unroll
            for (int i = 0; i < 8; i++) {
                acc[i][0] = ffma2(a[i], bv[0], acc[i][0]);
                acc[i][1] = ffma2(a[i], bv[1], acc[i][1]);
                acc[i][2] = ffma2(a[i], bv[2], acc[i][2]);
                acc[i][3] = ffma2(a[i], bv[3], acc[i][3]);
            }
        }
        __syncthreads();
        if (c + 1 < NC) {
#pragma unroll
            for (int i = 0; i < 8; i++) {
                int idx = tid + i * 128;
                int r = idx >> 3, kq = (idx & 7) * 4;
                *(float2*)&As[r][kq]     = make_float2(aR[i].x, aR[i].y);
                *(float2*)&As[r][kq + 2] = make_float2(aR[i].z, aR[i].w);
            }
#pragma unroll
            for (int p = 0; p < 8; p++) {
                int idx = tid + p * 128;
                Bt[idx >> 5][idx & 31] = bR[p];
            }
            __syncthreads();
        }
    }

#pragma unroll
    for (int i = 0; i < 8; i++) {
        int row = ty + 16 * i;
        float m = mask[(size_t)b * SS + s0 + row];
        float2 f0 = unpack2(acc[i][0]);
        float2 f1 = unpack2(acc[i][1]);
        float2 f2 = unpack2(acc[i][2]);
        float2 f3 = unpack2(acc[i][3]);
        size_t rb = ((size_t)(b * SS + s0 + row)) * HH;
        qs_buf[rb + tx]     = (f0.x + f0.y) * m;
        qs_buf[rb + tx + 8] = (f1.x + f1.y) * m;
        ks_buf[rb + tx]     = (f2.x + f2.y) * m;
        ks_buf[rb + tx + 8] = (f3.x + f3.y) * m;
    }
}

// ============================================================
// K1b: g[h][e] += ks[s][h]*H[s][e] ; hbar[e] += m[s]*H[s][e]
// streaming loads of hidden (no downstream reuse)
// ============================================================
__global__ void __launch_bounds__(256, 2)
k1b_accum(const float* __restrict__ hidden, const float* __restrict__ mask) {
    __shared__ u64 ks_dup[MT][16];
    __shared__ u64 m_dup[MT];

    const int tile = blockIdx.x;
    const int b = tile >> 5;
    const int s0 = (tile & 31) * MT;
    const int tid = threadIdx.x;
    const float* Ab = hidden + ((size_t)b * SS + s0) * HIDD;

#pragma unroll
    for (int p = 0; p < 8; p++) {
        int idx = tid + 256 * p;
        int r = idx >> 4, h = idx & 15;
        float v = ks_buf[((size_t)(b * SS + s0 + r)) * HH + h];
        ks_dup[r][h] = pack2(v, v);
    }
    if (tid < MT) {
        float m = mask[(size_t)b * SS + s0 + tid];
        m_dup[tid] = pack2(m, m);
    }
    __syncthreads();

    u64 g[16][2];
#pragma unroll
    for (int h = 0; h < 16; h++) { g[h][0] = 0ull; g[h][1] = 0ull; }
    u64 hb0 = 0ull, hb1 = 0ull;

    const float4* hrow = (const float4*)(Ab + tid * 4);
#pragma unroll 1
    for (int r0 = 0; r0 < MT; r0 += 4) {
        float4 hf[4];
#pragma unroll
        for (int u = 0; u < 4; u++)
            hf[u] = __ldcs(hrow + (size_t)(r0 + u) * (HIDD / 4));
#pragma unroll
        for (int u = 0; u < 4; u++) {
            ulonglong2 hv;
            hv.x = pack2(hf[u].x, hf[u].y);
            hv.y = pack2(hf[u].z, hf[u].w);
            u64 md = m_dup[r0 + u];
            hb0 = ffma2(hv.x, md, hb0);
            hb1 = ffma2(hv.y, md, hb1);
#pragma unroll
            for (int hh = 0; hh < 8; hh++) {
                ulonglong2 kp = *(const ulonglong2*)&ks_dup[r0 + u][hh * 2];
                g[2 * hh + 0][0] = ffma2(hv.x, kp.x, g[2 * hh + 0][0]);
                g[2 * hh + 0][1] = ffma2(hv.y, kp.x, g[2 * hh + 0][1]);
                g[2 * hh + 1][0] = ffma2(hv.x, kp.y, g[2 * hh + 1][0]);
                g[2 * hh + 1][1] = ffma2(hv.y, kp.y, g[2 * hh + 1][1]);
            }
        }
    }

#pragma unroll
    for (int h = 0; h < 16; h++) {
        float2 x = unpack2(g[h][0]), y = unpack2(g[h][1]);
        *(float4*)(g_scratch + ((size_t)tile * HH + h) * HIDD + tid * 4) =
            make_float4(x.x, x.y, y.x, y.y);
    }
    {
        float2 x = unpack2(hb0), y = unpack2(hb1);
        *(float4*)(hbar_scratch + (size_t)tile * HIDD + tid * 4) =
            make_float4(x.x, x.y, y.x, y.y);
    }
}

// ============================================================
// K2: per (b,h): reduce g partials AND hbar partials, then
// kv/mv = (gsum|hsum) . Wv rows. grid 128, block 1024.
// ============================================================
__global__ void __launch_bounds__(1024)
k2_kvmv(const float* __restrict__ Wv) {
    int b = blockIdx.x >> 4, h = blockIdx.x & 15;
    __shared__ float gsum[HIDD];
    __shared__ float hsum[HIDD];

    int e = threadIdx.x;
    {
        float ag[4], ah[4];
#pragma unroll
        for (int j = 0; j < 4; j++) { ag[j] = 0.f; ah[j] = 0.f; }
        const float* gb = g_scratch + (((size_t)b * TILES) * HH + h) * HIDD + e;
        const float* hb = hbar_scratch + ((size_t)b * TILES) * HIDD + e;
#pragma unroll
        for (int c = 0; c < TILES; c += 4) {
            float tg[4], th[4];
#pragma unroll
            for (int j = 0; j < 4; j++) tg[j] = gb[(size_t)(c + j) * HH * HIDD];
#pragma unroll
            for (int j = 0; j < 4; j++) th[j] = hb[(size_t)(c + j) * HIDD];
#pragma unroll
            for (int j = 0; j < 4; j++) { ag[j] += tg[j]; ah[j] += th[j]; }
        }
        gsum[e] = (ag[0] + ag[1]) + (ag[2] + ag[3]);
        hsum[e] = (ah[0] + ah[1]) + (ah[2] + ah[3]);
    }
    __syncthreads();

    int w = threadIdx.x >> 5, l = threadIdx.x & 31;
#pragma unroll
    for (int dd = 0; dd < 2; dd++) {
        int d = w * 2 + dd;
        const float* wvrow = Wv + (size_t)(h * DHH + d) * HIDD;
        float ak = 0.f, am = 0.f;
#pragma unroll 8
        for (int e2 = l; e2 < HIDD; e2 += 32) {
            float wv = __ldg(wvrow + e2);
            ak += gsum[e2] * wv;
            am += hsum[e2] * wv;
        }
#pragma unroll
        for (int off = 16; off > 0; off >>= 1) {
            ak += __shfl_xor_sync(0xffffffffu, ak, off);
            am += __shfl_xor_sync(0xffffffffu, am, off);
        }
        if (l == 0) {
            kv_buf[((b * HH + h) << 6) + d] = ak;
            mv_buf[((b * HH + h) << 6) + d] = am;
        }
    }
}

// ============================================================
// K3: out = (qs*mv + kv)*invlen ; 8 rows/block, streaming stores
// ============================================================
__global__ void k3_out(float* __restrict__ out) {
    int row0 = blockIdx.x << 3;
    int b = row0 >> 12;
    int t = threadIdx.x;
    int h = t >> 4;
    int d = (t & 15) << 2;
    float4 mv4 = *(const float4*)(mv_buf + ((b * HH + h) << 6) + d);
    float4 kv4 = *(const float4*)(kv_buf + ((b * HH + h) << 6) + d);
    float il = invlen_buf[b];
    float4 mvi = make_float4(mv4.x * il, mv4.y * il, mv4.z * il, mv4.w * il);
    float4 kvi = make_float4(kv4.x * il, kv4.y * il, kv4.z * il, kv4.w * il);
#pragma unroll
    for (int rr = 0; rr < 8; rr++) {
        int row = row0 + rr;
        float qsv = __ldg(qs_buf + (size_t)row * HH + h);
        float4 o;
        o.x = qsv * mvi.x + kvi.x;
        o.y = qsv * mvi.y + kvi.y;
        o.z = qsv * mvi.z + kvi.z;
        o.w = qsv * mvi.w + kvi.w;
        __stcs(((float4*)out) + (size_t)row * 256 + t, o);
    }
}

// ============================================================
extern "C" void kernel_launch(void* const* d_in, const int* in_sizes, int n_in,
                              void* d_out, int out_size) {
    const float* hidden = (const float*)d_in[0];
    const float* mask   = (const float*)d_in[1];
    const float* Wq     = (const float*)d_in[2];
    const float* Wk     = (const float*)d_in[3];
    const float* Wv     = (const float*)d_in[4];
    const float* aw     = (const float*)d_in[5];
    float* out = (float*)d_out;

    k0_weff<<<40, 256>>>(Wq, Wk, aw, mask);
    k1a_gemm<<<NBLK, 128>>>(hidden, mask);
    k1b_accum<<<NBLK, 256>>>(hidden, mask);
    k2_kvmv<<<BB * HH, 1024>>>(Wv);
    k3_out<<<BB * SS / 8, 256>>>(out);
}

// round 9
// speedup vs baseline: 1.7497x; 1.0103x over previous
#include <cuda_runtime.h>
#include <cstdint>

#define BB   8
#define SS   4096
#define HIDD 1024
#define HH   16
#define DHH  64

#define MT    128                // rows per tile
#define KC    32                 // k-chunk (floats)
#define NC    (HIDD / KC)        // 32
#define TILES 32
#define NBLK  (BB * TILES)       // 256

// ---------- static scratch ----------
__device__ float g_scratch[(size_t)NBLK * HH * HIDD]; // 16.8 MB
__device__ float hbar_scratch[(size_t)NBLK * HIDD];   // 1 MB
__device__ float wqk_eff[2 * HH * HIDD];
__device__ float qs_buf[(size_t)BB * SS * HH];        // 2 MB
__device__ float ks_buf[(size_t)BB * SS * HH];        // 2 MB
__device__ float gsum_buf[BB * HH * HIDD];            // 512 KB
__device__ float hsum_buf[BB * HIDD];                 // 32 KB
__device__ float kv_buf[BB * HH * DHH];
__device__ float mv_buf[BB * HH * DHH];
__device__ float invlen_buf[BB];

typedef unsigned long long u64;

__device__ __forceinline__ u64 ffma2(u64 a, u64 b, u64 c) {
    u64 d;
    asm("fma.rn.f32x2 %0, %1, %2, %3;" : "=l"(d) : "l"(a), "l"(b), "l"(c));
    return d;
}
__device__ __forceinline__ u64 pack2(float x, float y) {
    u64 r; asm("mov.b64 %0, {%1,%2};" : "=l"(r) : "f"(x), "f"(y)); return r;
}
__device__ __forceinline__ float2 unpack2(u64 v) {
    float2 r; asm("mov.b64 {%0,%1}, %2;" : "=f"(r.x), "=f"(r.y) : "l"(v)); return r;
}
__device__ __forceinline__ uint32_t smem_u32(const void* p) {
    uint32_t a;
    asm("{ .reg .u64 t; cvta.to.shared.u64 t, %1; cvt.u32.u64 %0, t; }" : "=r"(a) : "l"(p));
    return a;
}
__device__ __forceinline__ void cp16(uint32_t dst, const void* src) {
    asm volatile("cp.async.ca.shared.global [%0], [%1], 16;" :: "r"(dst), "l"(src) : "memory");
}
__device__ __forceinline__ void cp_commit() {
    asm volatile("cp.async.commit_group;" ::: "memory");
}
__device__ __forceinline__ void cp_wait0() {
    asm volatile("cp.async.wait_group 0;" ::: "memory");
}

// ============================================================
// K0: blocks 0..31 weff ; blocks 32..39 invlen
// ============================================================
__global__ void k0_weff(const float* __restrict__ Wq,
                        const float* __restrict__ Wk,
                        const float* __restrict__ aw,
                        const float* __restrict__ mask) {
    if (blockIdx.x >= 32) {
        int b = blockIdx.x - 32;
        __shared__ float red[256];
        float s = 0.f;
        for (int i = threadIdx.x; i < SS; i += 256) s += mask[(size_t)b * SS + i];
        red[threadIdx.x] = s;
        __syncthreads();
        for (int st = 128; st > 0; st >>= 1) {
            if (threadIdx.x < st) red[threadIdx.x] += red[threadIdx.x + st];
            __syncthreads();
        }
        if (threadIdx.x == 0) invlen_buf[b] = 1.f / red[0];
        return;
    }
    int ch = blockIdx.x >> 4, h = blockIdx.x & 15;
    const float* W = ch ? Wk : Wq;
    __shared__ float a_sh[DHH];
    if (threadIdx.x < DHH) a_sh[threadIdx.x] = aw[h * DHH + threadIdx.x];
    __syncthreads();
    for (int e = threadIdx.x; e < HIDD; e += blockDim.x) {
        float acc = 0.f;
#pragma unroll 8
        for (int d = 0; d < DHH; d++)
            acc += a_sh[d] * W[(size_t)(h * DHH + d) * HIDD + e];
        wqk_eff[(ch * HH + h) * HIDD + e] = acc;
    }
}

// ============================================================
// K1a: GEMM C[128x32] = tile x wqk_eff^T, 128 threads, tile 8x4,
// k-paired FFMA2; cp.async double-buffered staging (overlap DRAM with FMA).
// As/Bt row stride 36 floats (=144B, 16B-aligned targets, conflict-free).
// ============================================================
__global__ void __launch_bounds__(128, 3)
k1a_gemm(const float* __restrict__ hidden, const float* __restrict__ mask) {
    __shared__ float As[2][MT][36];
    __shared__ float Bt[2][32][36];

    const int tile = blockIdx.x;
    const int b = tile >> 5;
    const int s0 = (tile & 31) * MT;
    const int tid = threadIdx.x;
    const int tx = tid & 7;
    const int ty = tid >> 3;

    const float* Ab = hidden + ((size_t)b * SS + s0) * HIDD;

    // per-thread staging units (constant)
    // A: 8 units of 16B; unit = tid + i*128 -> row unit>>3, kq unit&7
    // B: 2 units of 16B; unit = tid + p*128 -> vec unit>>3, kq unit&7
    uint32_t a_dst[2][8], b_dst[2][2];
    const float* a_src[8];
    const float* b_src[2];
#pragma unroll
    for (int i = 0; i < 8; i++) {
        int unit = tid + i * 128;
        int r = unit >> 3, kq = unit & 7;
        a_dst[0][i] = smem_u32(&As[0][r][kq * 4]);
        a_dst[1][i] = smem_u32(&As[1][r][kq * 4]);
        a_src[i] = Ab + (size_t)r * HIDD + kq * 4;
    }
#pragma unroll
    for (int p = 0; p < 2; p++) {
        int unit = tid + p * 128;
        int v = unit >> 3, kq = unit & 7;
        b_dst[0][p] = smem_u32(&Bt[0][v][kq * 4]);
        b_dst[1][p] = smem_u32(&Bt[1][v][kq * 4]);
        b_src[p] = wqk_eff + (size_t)v * HIDD + kq * 4;
    }

    u64 acc[8][4];
#pragma unroll
    for (int i = 0; i < 8; i++)
#pragma unroll
        for (int j = 0; j < 4; j++) acc[i][j] = 0ull;

    // ---- prologue: stage chunk 0 into buffer 0 ----
#pragma unroll
    for (int i = 0; i < 8; i++) cp16(a_dst[0][i], a_src[i]);
#pragma unroll
    for (int p = 0; p < 2; p++) cp16(b_dst[0][p], b_src[p]);
    cp_commit();
    cp_wait0();
    __syncthreads();

    // ---- main loop: double-buffered ----
#pragma unroll 1
    for (int c = 0; c < NC; c++) {
        const int cur = c & 1, nxt = cur ^ 1;
        if (c + 1 < NC) {
            int k0 = (c + 1) * KC;
#pragma unroll
            for (int i = 0; i < 8; i++) cp16(a_dst[nxt][i], a_src[i] + k0);
#pragma unroll
            for (int p = 0; p < 2; p++) cp16(b_dst[nxt][p], b_src[p] + k0);
            cp_commit();
        }
#pragma unroll
        for (int k = 0; k < KC; k += 2) {
            u64 a[8], bv[4];
#pragma unroll
            for (int i = 0; i < 8; i++) a[i] = *(const u64*)&As[cur][ty + 16 * i][k];
#pragma unroll
            for (int j = 0; j < 4; j++) bv[j] = *(const u64*)&Bt[cur][tx + 8 * j][k];
#pragma unroll
            for (int i = 0; i < 8; i++) {
                acc[i][0] = ffma2(a[i], bv[0], acc[i][0]);
                acc[i][1] = ffma2(a[i], bv[1], acc[i][1]);
                acc[i][2] = ffma2(a[i], bv[2], acc[i][2]);
                acc[i][3] = ffma2(a[i], bv[3], acc[i][3]);
            }
        }
        if (c + 1 < NC) cp_wait0();
        __syncthreads();
    }

    // ---- epilogue: sum k-pair lanes, apply mask, write qs/ks ----
#pragma unroll
    for (int i = 0; i < 8; i++) {
        int row = ty + 16 * i;
        float m = mask[(size_t)b * SS + s0 + row];
        float2 f0 = unpack2(acc[i][0]);
        float2 f1 = unpack2(acc[i][1]);
        float2 f2 = unpack2(acc[i][2]);
        float2 f3 = unpack2(acc[i][3]);
        size_t rb = ((size_t)(b * SS + s0 + row)) * HH;
        qs_buf[rb + tx]     = (f0.x + f0.y) * m;
        qs_buf[rb + tx + 8] = (f1.x + f1.y) * m;
        ks_buf[rb + tx]     = (f2.x + f2.y) * m;
        ks_buf[rb + tx + 8] = (f3.x + f3.y) * m;
    }
}

// ============================================================
// K1b: g[h][e] += ks[s][h]*H[s][e] ; hbar[e] += m[s]*H[s][e]
// ============================================================
__global__ void __launch_bounds__(256, 2)
k1b_accum(const float* __restrict__ hidden, const float* __restrict__ mask) {
    __shared__ u64 ks_dup[MT][16];
    __shared__ u64 m_dup[MT];

    const int tile = blockIdx.x;
    const int b = tile >> 5;
    const int s0 = (tile & 31) * MT;
    const int tid = threadIdx.x;
    const float* Ab = hidden + ((size_t)b * SS + s0) * HIDD;

#pragma unroll
    for (int p = 0; p < 8; p++) {
        int idx = tid + 256 * p;
        int r = idx >> 4, h = idx & 15;
        float v = ks_buf[((size_t)(b * SS + s0 + r)) * HH + h];
        ks_dup[r][h] = pack2(v, v);
    }
    if (tid < MT) {
        float m = mask[(size_t)b * SS + s0 + tid];
        m_dup[tid] = pack2(m, m);
    }
    __syncthreads();

    u64 g[16][2];
#pragma unroll
    for (int h = 0; h < 16; h++) { g[h][0] = 0ull; g[h][1] = 0ull; }
    u64 hb0 = 0ull, hb1 = 0ull;

    const float4* hrow = (const float4*)(Ab + tid * 4);
#pragma unroll 1
    for (int r0 = 0; r0 < MT; r0 += 4) {
        float4 hf[4];
#pragma unroll
        for (int u = 0; u < 4; u++)
            hf[u] = __ldcs(hrow + (size_t)(r0 + u) * (HIDD / 4));
#pragma unroll
        for (int u = 0; u < 4; u++) {
            ulonglong2 hv;
            hv.x = pack2(hf[u].x, hf[u].y);
            hv.y = pack2(hf[u].z, hf[u].w);
            u64 md = m_dup[r0 + u];
            hb0 = ffma2(hv.x, md, hb0);
            hb1 = ffma2(hv.y, md, hb1);
#pragma unroll
            for (int hh = 0; hh < 8; hh++) {
                ulonglong2 kp = *(const ulonglong2*)&ks_dup[r0 + u][hh * 2];
                g[2 * hh + 0][0] = ffma2(hv.x, kp.x, g[2 * hh + 0][0]);
                g[2 * hh + 0][1] = ffma2(hv.y, kp.x, g[2 * hh + 0][1]);
                g[2 * hh + 1][0] = ffma2(hv.x, kp.y, g[2 * hh + 1][0]);
                g[2 * hh + 1][1] = ffma2(hv.y, kp.y, g[2 * hh + 1][1]);
            }
        }
    }

#pragma unroll
    for (int h = 0; h < 16; h++) {
        float2 x = unpack2(g[h][0]), y = unpack2(g[h][1]);
        *(float4*)(g_scratch + ((size_t)tile * HH + h) * HIDD + tid * 4) =
            make_float4(x.x, x.y, y.x, y.y);
    }
    {
        float2 x = unpack2(hb0), y = unpack2(hb1);
        *(float4*)(hbar_scratch + (size_t)tile * HIDD + tid * 4) =
            make_float4(x.x, x.y, y.x, y.y);
    }
}

// ============================================================
// K2r: parallel reduction of g_scratch -> gsum_buf and
//      hbar_scratch -> hsum_buf. grid 544 (512 g + 32 hbar), block 256.
// ============================================================
__global__ void __launch_bounds__(256)
k2r_reduce() {
    int bid = blockIdx.x;
    if (bid < 512) {
        int b = bid >> 6, h = (bid >> 2) & 15, seg = bid & 3;
        int e = seg * 256 + threadIdx.x;
        const float* base = g_scratch + (((size_t)b * TILES) * HH + h) * HIDD + e;
        float a[4];
#pragma unroll
        for (int j = 0; j < 4; j++) a[j] = 0.f;
#pragma unroll
        for (int c = 0; c < TILES; c += 4) {
            float t[4];
#pragma unroll
            for (int j = 0; j < 4; j++) t[j] = base[(size_t)(c + j) * HH * HIDD];
#pragma unroll
            for (int j = 0; j < 4; j++) a[j] += t[j];
        }
        gsum_buf[((b * HH + h) << 10) + e] = (a[0] + a[1]) + (a[2] + a[3]);
    } else {
        int bid2 = bid - 512;
        int b = bid2 >> 2, seg = bid2 & 3;
        int e = seg * 256 + threadIdx.x;
        const float* base = hbar_scratch + ((size_t)b * TILES) * HIDD + e;
        float a[4];
#pragma unroll
        for (int j = 0; j < 4; j++) a[j] = 0.f;
#pragma unroll
        for (int c = 0; c < TILES; c += 4) {
            float t[4];
#pragma unroll
            for (int j = 0; j < 4; j++) t[j] = base[(size_t)(c + j) * HIDD];
#pragma unroll
            for (int j = 0; j < 4; j++) a[j] += t[j];
        }
        hsum_buf[(b << 10) + e] = (a[0] + a[1]) + (a[2] + a[3]);
    }
}

// ============================================================
// K2d: per (b,h): kv/mv = (gsum|hsum) . Wv rows. grid 128, block 256.
// ============================================================
__global__ void __launch_bounds__(256)
k2d_dot(const float* __restrict__ Wv) {
    int b = blockIdx.x >> 4, h = blockIdx.x & 15;
    __shared__ float gsum[HIDD];
    __shared__ float hsum[HIDD];

    {
        int t4 = threadIdx.x * 4;
        *(float4*)&gsum[t4] = *(const float4*)(gsum_buf + ((b * HH + h) << 10) + t4);
        *(float4*)&hsum[t4] = *(const float4*)(hsum_buf + (b << 10) + t4);
    }
    __syncthreads();

    int w = threadIdx.x >> 5, l = threadIdx.x & 31;
#pragma unroll
    for (int dd = 0; dd < 8; dd++) {
        int d = w * 8 + dd;
        const float* wvrow = Wv + (size_t)(h * DHH + d) * HIDD;
        float ak = 0.f, am = 0.f;
#pragma unroll 8
        for (int e2 = l; e2 < HIDD; e2 += 32) {
            float wv = __ldg(wvrow + e2);
            ak += gsum[e2] * wv;
            am += hsum[e2] * wv;
        }
#pragma unroll
        for (int off = 16; off > 0; off >>= 1) {
            ak += __shfl_xor_sync(0xffffffffu, ak, off);
            am += __shfl_xor_sync(0xffffffffu, am, off);
        }
        if (l == 0) {
            kv_buf[((b * HH + h) << 6) + d] = ak;
            mv_buf[((b * HH + h) << 6) + d] = am;
        }
    }
}

// ============================================================
// K3: out = (qs*mv + kv)*invlen
// ============================================================
__global__ void k3_out(float* __restrict__ out) {
    int row0 = blockIdx.x << 3;
    int b = row0 >> 12;
    int t = threadIdx.x;
    int h = t >> 4;
    int d = (t & 15) << 2;
    float4 mv4 = *(const float4*)(mv_buf + ((b * HH + h) << 6) + d);
    float4 kv4 = *(const float4*)(kv_buf + ((b * HH + h) << 6) + d);
    float il = invlen_buf[b];
    float4 mvi = make_float4(mv4.x * il, mv4.y * il, mv4.z * il, mv4.w * il);
    float4 kvi = make_float4(kv4.x * il, kv4.y * il, kv4.z * il, kv4.w * il);
#pragma unroll
    for (int rr = 0; rr < 8; rr++) {
        int row = row0 + rr;
        float qsv = __ldg(qs_buf + (size_t)row * HH + h);
        float4 o;
        o.x = qsv * mvi.x + kvi.x;
        o.y = qsv * mvi.y + kvi.y;
        o.z = qsv * mvi.z + kvi.z;
        o.w = qsv * mvi.w + kvi.w;
        __stcs(((float4*)out) + (size_t)row * 256 + t, o);
    }
}

// ============================================================
extern "C" void kernel_launch(void* const* d_in, const int* in_sizes, int n_in,
                              void* d_out, int out_size) {
    const float* hidden = (const float*)d_in[0];
    const float* mask   = (const float*)d_in[1];
    const float* Wq     = (const float*)d_in[2];
    const float* Wk     = (const float*)d_in[3];
    const float* Wv     = (const float*)d_in[4];
    const float* aw     = (const float*)d_in[5];
    float* out = (float*)d_out;

    k0_weff<<<40, 256>>>(Wq, Wk, aw, mask);
    k1a_gemm<<<NBLK, 128>>>(hidden, mask);
    k1b_accum<<<NBLK, 256>>>(hidden, mask);
    k2r_reduce<<<544, 256>>>();
    k2d_dot<<<BB * HH, 256>>>(Wv);
    k3_out<<<BB * SS / 8, 256>>>(out);
}